// round 11
// baseline (speedup 1.0000x reference)
#include <cuda_runtime.h>

#define KCH    32
#define HW     64
#define TSTEPS 100
#define PLANE  4096
#define NCTA   128
#define NTHR   512
#define ROWS_L 60
#define RP     65

// State X_{t+1} lives directly in out[n, t, k, :, :]. No WAR hazards exist
// (each step writes a fresh frame), so sync is pure RAW visibility:
//   feat of CTA (n,k,h) needs group (n,h)'s 32 CTAs  -> group barrier
//   halo of CTA (n,k,h) needs only CTA (n,k,h^1)     -> partner flag

// Per-group (n*2+h) barrier: atomicAdd arrive, 32nd arrival resets cnt and
// release-stores gen. gens/flags monotonic across graph replays (relative
// compares only).
__device__ unsigned g_cnt[4], g_gen[4];
__device__ unsigned g_flags[NCTA];

__device__ __forceinline__ unsigned ld_acq(const unsigned* p) {
    unsigned v;
    asm volatile("ld.acquire.gpu.global.u32 %0, [%1];" : "=r"(v) : "l"(p) : "memory");
    return v;
}
__device__ __forceinline__ void st_rel(unsigned* p, unsigned v) {
    asm volatile("st.release.gpu.global.u32 [%0], %1;" :: "l"(p), "r"(v) : "memory");
}

__global__ void __launch_bounds__(NTHR, 1)
persist_kernel(const float* __restrict__ inbound,
               const float* __restrict__ Wf,
               const float* __restrict__ bf,
               const float* __restrict__ Ws,
               const float* __restrict__ bs,
               float* __restrict__ out)
{
    extern __shared__ float sm[];
    float* Rb0 = sm;                           // [60][65] X halo rows (even t)
    float* Rb1 = Rb0 + ROWS_L * RP;            // [60][65] X halo rows (odd t)
    float* H29 = Rb1 + ROWS_L * RP;            // [60][65] 29-wide horizontal sums
    float* H9  = H29 + ROWS_L * RP;            // [60][65] 9-wide horizontal sums
    float* S   = H9  + ROWS_L * RP;            // [32][64] feat + 0.5*inb + bf
    float* WfS = S + 32 * HW;
    __shared__ unsigned sb[2];

    const int b   = blockIdx.x;                // 0..127
    const int tid = threadIdx.x;
    const int n   = b >> 6;
    const int k   = (b & 63) >> 1;
    const int h   = b & 1;
    const int r0  = h << 5;
    const int partner = b ^ 1;
    const int g   = n * 2 + h;                 // barrier group
    const size_t plane_off = (size_t)k * PLANE;

    if (tid < KCH) WfS[tid] = Wf[k * KCH + tid];
    if (tid == 0) { sb[0] = ld_acq(&g_gen[g]); sb[1] = ld_acq(&g_flags[b]); }

    const float bf_k = bf[k];
    const float bs_k = bs[k];
    const float inh  = Ws[k * 841];                 // uniform inhibition value
    const float emin = Ws[k * 841 + 420] - inh;     // center excitation minus inh

    // zero R buffers + H29 + H9 (X_0 = 0; zero-edge-row H entries never rewritten)
    for (int i = tid; i < 4 * ROWS_L * RP; i += NTHR) sm[i] = 0.f;

    // ---- feat mapping: (row rr_f, 4 contiguous pixels) ----
    const int rr_f = tid >> 4;                 // 0..31
    const int w0_f = (tid & 15) << 2;
    const float4 inb4 = *(const float4*)(inbound + (size_t)(n * KCH + k) * PLANE
                                         + (r0 + rr_f) * HW + w0_f);
    const float base0 = 0.5f * inb4.x + bf_k;
    const float base1 = 0.5f * inb4.y + bf_k;
    const float base2 = 0.5f * inb4.z + bf_k;
    const float base3 = 0.5f * inb4.w + bf_k;
    *(float4*)&S[rr_f * HW + w0_f] = make_float4(base0, base1, base2, base3);

    // ---- partner-halo mapping (threads 0..223): 14 rows x 16 float4 ----
    // h=0: global rows 32..45 -> j=46..59 ; h=1: global rows 18..31 -> j=0..13
    const int pj0 = h ? 0 : 46;
    const int pg0 = h ? 18 : 32;
    const int jr  = tid >> 4;
    const int wq  = (tid & 15) << 2;

    // ---- V mapping: 512 threads, (column, 4-row segment) ----
    const int w_v = tid & 63;
    const int rb  = (tid >> 6) << 2;

    __syncthreads();
    const unsigned gen0 = sb[0], fbase = sb[1];

    for (int t = 0; t < TSTEPS; t++) {
        float* R_cur = (t & 1) ? Rb1 : Rb0;
        float* R_nxt = (t & 1) ? Rb0 : Rb1;
        const float* frame_prev = out + ((size_t)(n * TSTEPS + t - 1) * KCH) * PLANE;
        float*       frame_cur  = out + ((size_t)(n * TSTEPS + t)     * KCH) * PLANE;

        // ======== feat (t>0): all threads poll group gen, then S = base + Wf@X_t
        if (t > 0) {
            const unsigned gtgt = gen0 + (unsigned)t;
            while ((int)(ld_acq(&g_gen[g]) - gtgt) < 0) { }

            const float4* bp = (const float4*)(frame_prev + (r0 + rr_f) * HW + w0_f);
            float a0 = base0, a1 = base1, a2 = base2, a3 = base3;
            #pragma unroll
            for (int i = 0; i < KCH; i++) {
                const float wv = WfS[i];
                const float4 x = bp[i * (PLANE / 4)];
                a0 += wv * x.x; a1 += wv * x.y;
                a2 += wv * x.z; a3 += wv * x.w;
            }
            *(float4*)&S[rr_f * HW + w0_f] = make_float4(a0, a1, a2, a3);
        }
        __syncthreads();       // orders shadow H writes + S writes vs V reads

        // ======== V: vertical box sums + combine + emit ========
        {
            float b29a = 0.f, b29b = 0.f, b9 = 0.f;
            #pragma unroll
            for (int d = 0; d < 14; d++) {
                b29a += H29[(rb + d) * RP + w_v];
                b29b += H29[(rb + 14 + d) * RP + w_v];
            }
            float b29 = b29a + b29b + H29[(rb + 28) * RP + w_v];
            #pragma unroll
            for (int d = 0; d < 9; d++) b9 += H9[(rb + 10 + d) * RP + w_v];

            #pragma unroll
            for (int r = 0; r < 4; r++) {
                const int rr = rb + r;
                const int j  = rr + 14;
                if (r > 0) {
                    b29 += H29[(rr + 28) * RP + w_v] - H29[(rr - 1) * RP + w_v];
                    b9  += H9 [(j + 4)  * RP + w_v] - H9 [(j - 5)  * RP + w_v];
                }
                const float sp = inh * b29 + emin * b9 + bs_k;
                const float xo = R_cur[j * RP + w_v];
                const float xn = 0.8f * xo + 0.2f * fmaxf(S[rr * HW + w_v] + sp, 0.f);
                R_nxt[j * RP + w_v] = xn;
                frame_cur[plane_off + (size_t)(r0 + rr) * HW + w_v] = xn;
            }
        }

        if (t == TSTEPS - 1) break;

        __syncthreads();       // frame/R_nxt stores done; H/S/R_cur reads done
        const unsigned ftgt = fbase + (unsigned)t + 1u;
        if (tid == 0) {
            __threadfence();   // publish this CTA's frame stores
            st_rel(&g_flags[b], ftgt);
            if (atomicAdd(&g_cnt[g], 1u) == 31u) {
                g_cnt[g] = 0;  // ordered before release below
                st_rel(&g_gen[g], gen0 + (unsigned)t + 1u);
            }
        }

        // ======== shadow work (no global wait needed for interior) ========
        if (tid >= 256) {
            // interior rows j=14..45: H from R_nxt written by V (local, ready now)
            const int id = tid - 256;          // 0..255
            const int j  = 14 + (id >> 3);
            const int s  = (id & 7) << 3;
            const float* row = &R_nxt[j * RP];
            float v[36];
            #pragma unroll
            for (int d = 0; d < 36; d++) {
                const int w = s - 14 + d;
                v[d] = (w >= 0 && w < HW) ? row[w] : 0.f;
            }
            float sa = 0.f, sc = 0.f;
            #pragma unroll
            for (int d = 0; d < 14; d++) { sa += v[d]; sc += v[d + 14]; }
            float s29 = sa + sc + v[28];
            H29[j * RP + s] = s29;
            #pragma unroll
            for (int p = 1; p < 8; p++) {
                s29 += v[p + 28] - v[p - 1];
                H29[j * RP + s + p] = s29;
            }
            float s9 = 0.f;
            #pragma unroll
            for (int d = 10; d < 19; d++) s9 += v[d];
            H9[j * RP + s] = s9;
            #pragma unroll
            for (int p = 1; p < 8; p++) {
                s9 += v[p + 18] - v[p + 9];
                H9[j * RP + s + p] = s9;
            }
        } else if (tid < 224) {
            // partner rows: poll partner flag, deposit, then H for those rows
            while ((int)(ld_acq(&g_flags[partner]) - ftgt) < 0) { }
            const float4 v4 = *(const float4*)(frame_cur + plane_off
                                               + (pg0 + jr) * HW + wq);
            float* rp = &R_nxt[(pj0 + jr) * RP + wq];
            rp[0] = v4.x; rp[1] = v4.y; rp[2] = v4.z; rp[3] = v4.w;
            asm volatile("bar.sync 1, 224;" ::: "memory");
            if (tid < 112) {
                const int j = pj0 + (tid >> 3);
                const int s = (tid & 7) << 3;
                const float* row = &R_nxt[j * RP];
                float v[36];
                #pragma unroll
                for (int d = 0; d < 36; d++) {
                    const int w = s - 14 + d;
                    v[d] = (w >= 0 && w < HW) ? row[w] : 0.f;
                }
                float sa = 0.f, sc = 0.f;
                #pragma unroll
                for (int d = 0; d < 14; d++) { sa += v[d]; sc += v[d + 14]; }
                float s29 = sa + sc + v[28];
                H29[j * RP + s] = s29;
                #pragma unroll
                for (int p = 1; p < 8; p++) {
                    s29 += v[p + 28] - v[p - 1];
                    H29[j * RP + s + p] = s29;
                }
                float s9 = 0.f;
                #pragma unroll
                for (int d = 10; d < 19; d++) s9 += v[d];
                H9[j * RP + s] = s9;
                #pragma unroll
                for (int p = 1; p < 8; p++) {
                    s9 += v[p + 18] - v[p + 9];
                    H9[j * RP + s + p] = s9;
                }
            }
        }
        // loop top: per-thread gen poll, then feat; post-feat __syncthreads
        // orders all shadow H writes before V reads.
    }
}

extern "C" void kernel_launch(void* const* d_in, const int* in_sizes, int n_in,
                              void* d_out, int out_size)
{
    const float* inbound = (const float*)d_in[0];
    const float* Wf      = (const float*)d_in[1];
    const float* bf      = (const float*)d_in[2];
    const float* Ws      = (const float*)d_in[3];
    const float* bs      = (const float*)d_in[4];
    float* out = (float*)d_out;

    const int smem_bytes = (4 * ROWS_L * RP + 32 * HW + KCH) * sizeof(float) + 16;
    static bool attr_set = false;
    if (!attr_set) {
        cudaFuncSetAttribute(persist_kernel,
                             cudaFuncAttributeMaxDynamicSharedMemorySize, smem_bytes);
        attr_set = true;
    }
    persist_kernel<<<NCTA, NTHR, smem_bytes>>>(inbound, Wf, bf, Ws, bs, out);
}

// round 13
// speedup vs baseline: 1.5247x; 1.5247x over previous
#include <cuda_runtime.h>

#define KCH    32
#define HW     64
#define TSTEPS 100
#define PLANE  4096
#define NCTA   128
#define NCTA_B 64          // CTAs per batch (independent barrier groups)
#define NTHR   512
#define ROWS_L 60
#define RP     65

// State X_{t+1} lives directly in out[n, t, k, :, :].
// Per-batch barrier (atomicAdd arrive + gen release) + per-CTA partner flags.
// gen/flags monotonic across graph replays (relative compares only); cnt reset
// to 0 by each releaser.
__device__ unsigned g_bar_cnt[2], g_bar_gen[2];
__device__ unsigned g_flags[NCTA];

__device__ __forceinline__ unsigned ld_acq(const unsigned* p) {
    unsigned v;
    asm volatile("ld.acquire.gpu.global.u32 %0, [%1];" : "=r"(v) : "l"(p) : "memory");
    return v;
}
__device__ __forceinline__ void st_rel(unsigned* p, unsigned v) {
    asm volatile("st.release.gpu.global.u32 [%0], %1;" :: "l"(p), "r"(v) : "memory");
}

// Horizontal box sums (widths 29 and 9) for one 8-pixel segment of row j.
__device__ __forceinline__ void h_segment(const float* __restrict__ row,
                                          float* __restrict__ H29,
                                          float* __restrict__ H9,
                                          int j, int s)
{
    float v[36];
    #pragma unroll
    for (int d = 0; d < 36; d++) {
        const int w = s - 14 + d;
        v[d] = (w >= 0 && w < HW) ? row[w] : 0.f;
    }
    float sa = 0.f, sc = 0.f;
    #pragma unroll
    for (int d = 0; d < 14; d++) { sa += v[d]; sc += v[d + 14]; }
    float s29 = sa + sc + v[28];
    H29[j * RP + s] = s29;
    #pragma unroll
    for (int p = 1; p < 8; p++) {
        s29 += v[p + 28] - v[p - 1];
        H29[j * RP + s + p] = s29;
    }
    float s9 = 0.f;
    #pragma unroll
    for (int d = 10; d < 19; d++) s9 += v[d];
    H9[j * RP + s] = s9;
    #pragma unroll
    for (int p = 1; p < 8; p++) {
        s9 += v[p + 18] - v[p + 9];
        H9[j * RP + s + p] = s9;
    }
}

__global__ void __launch_bounds__(NTHR, 1)
persist_kernel(const float* __restrict__ inbound,
               const float* __restrict__ Wf,
               const float* __restrict__ bf,
               const float* __restrict__ Ws,
               const float* __restrict__ bs,
               float* __restrict__ out)
{
    extern __shared__ float sm[];
    float* Rb0 = sm;                           // [60][65] X halo rows (even t)
    float* Rb1 = Rb0 + ROWS_L * RP;            // [60][65] X halo rows (odd t)
    float* H29 = Rb1 + ROWS_L * RP;            // [60][65] 29-wide horizontal sums
    float* H9  = H29 + ROWS_L * RP;            // [60][65] 9-wide horizontal sums
    float* S   = H9  + ROWS_L * RP;            // [32][64] feat + 0.5*inb + bf
    float* WfS = S + 32 * HW;
    __shared__ unsigned sb[2];

    const int b   = blockIdx.x;                // 0..127
    const int tid = threadIdx.x;
    const int n   = b >> 6;
    const int k   = (b & 63) >> 1;
    const int h   = b & 1;
    const int r0  = h << 5;
    const int partner = b ^ 1;
    const size_t plane_off = (size_t)k * PLANE;

    if (tid < KCH) WfS[tid] = Wf[k * KCH + tid];
    if (tid == 0) { sb[0] = ld_acq(&g_bar_gen[n]); sb[1] = ld_acq(&g_flags[b]); }

    const float bf_k = bf[k];
    const float bs_k = bs[k];
    const float inh  = Ws[k * 841];                 // uniform inhibition value
    const float emin = Ws[k * 841 + 420] - inh;     // center excitation minus inh

    // zero R buffers + H29 + H9 (X_0 = 0; zero-edge-row H entries never rewritten)
    for (int i = tid; i < 4 * ROWS_L * RP; i += NTHR) sm[i] = 0.f;

    // ---- feat mapping: (row rr_f, 4 contiguous pixels) ----
    const int rr_f = tid >> 4;                 // 0..31
    const int w0_f = (tid & 15) << 2;
    const float4 inb4 = *(const float4*)(inbound + (size_t)(n * KCH + k) * PLANE
                                         + (r0 + rr_f) * HW + w0_f);
    const float base0 = 0.5f * inb4.x + bf_k;
    const float base1 = 0.5f * inb4.y + bf_k;
    const float base2 = 0.5f * inb4.z + bf_k;
    const float base3 = 0.5f * inb4.w + bf_k;
    *(float4*)&S[rr_f * HW + w0_f] = make_float4(base0, base1, base2, base3);

    // ---- partner-halo mapping (threads 0..223): 14 rows x 16 float4 ----
    // h=0: global rows 32..45 -> j=46..59 ; h=1: global rows 18..31 -> j=0..13
    const int pj0 = h ? 0 : 46;
    const int pg0 = h ? 18 : 32;
    const int jr  = tid >> 4;
    const int wq  = (tid & 15) << 2;

    // ---- V mapping: 512 threads, (column, 4-row segment) ----
    const int w_v = tid & 63;
    const int rb  = (tid >> 6) << 2;

    __syncthreads();
    const unsigned gen0 = sb[0], fbase = sb[1];

    for (int t = 0; t < TSTEPS; t++) {
        float* R_cur = (t & 1) ? Rb1 : Rb0;
        float* R_nxt = (t & 1) ? Rb0 : Rb1;
        const float* frame_prev = out + ((size_t)(n * TSTEPS + t - 1) * KCH) * PLANE;
        float*       frame_cur  = out + ((size_t)(n * TSTEPS + t)     * KCH) * PLANE;

        // ======== feat (t>0): S = base + Wf @ X_t ========
        if (t > 0) {
            const float4* bp = (const float4*)(frame_prev + (r0 + rr_f) * HW + w0_f);
            float a0 = base0, a1 = base1, a2 = base2, a3 = base3;
            #pragma unroll
            for (int i = 0; i < KCH; i++) {
                const float wv = WfS[i];
                const float4 x = bp[i * (PLANE / 4)];
                a0 += wv * x.x; a1 += wv * x.y;
                a2 += wv * x.z; a3 += wv * x.w;
            }
            *(float4*)&S[rr_f * HW + w0_f] = make_float4(a0, a1, a2, a3);
            __syncthreads();
        }

        // ======== V: vertical box sums (H from previous tail) + combine ========
        {
            float b29a = 0.f, b29b = 0.f, b9 = 0.f;
            #pragma unroll
            for (int d = 0; d < 14; d++) {
                b29a += H29[(rb + d) * RP + w_v];
                b29b += H29[(rb + 14 + d) * RP + w_v];
            }
            float b29 = b29a + b29b + H29[(rb + 28) * RP + w_v];
            #pragma unroll
            for (int d = 0; d < 9; d++) b9 += H9[(rb + 10 + d) * RP + w_v];

            #pragma unroll
            for (int r = 0; r < 4; r++) {
                const int rr = rb + r;
                const int j  = rr + 14;
                if (r > 0) {
                    b29 += H29[(rr + 28) * RP + w_v] - H29[(rr - 1) * RP + w_v];
                    b9  += H9 [(j + 4)  * RP + w_v] - H9 [(j - 5)  * RP + w_v];
                }
                const float sp = inh * b29 + emin * b9 + bs_k;
                const float xo = R_cur[j * RP + w_v];
                const float xn = 0.8f * xo + 0.2f * fmaxf(S[rr * HW + w_v] + sp, 0.f);
                R_nxt[j * RP + w_v] = xn;                  // interior rows for t+1
                frame_cur[plane_off + (size_t)(r0 + rr) * HW + w_v] = xn;
            }
        }

        if (t == TSTEPS - 1) break;

        __syncthreads();                       // frame/R_nxt stores + smem reads done
        const unsigned ftgt = fbase + (unsigned)t + 1u;
        const unsigned gtgt = gen0  + (unsigned)t + 1u;
        if (tid == 0) {
            __threadfence();                   // publish this CTA's frame stores
            st_rel(&g_flags[b], ftgt);
            if (atomicAdd(&g_bar_cnt[n], 1u) == NCTA_B - 1) {
                g_bar_cnt[n] = 0;
                st_rel(&g_bar_gen[n], gtgt);
            }
            // wait only for partner before touching its halo rows
            while ((int)(ld_acq(&g_flags[partner]) - ftgt) < 0) { }
        }
        __syncthreads();

        // ======== shadow: halo prefetch overlapped with interior H ========
        float4 hv;
        if (tid < 224)                         // issue halo LDGs (latency hidden below)
            hv = *(const float4*)(frame_cur + plane_off + (pg0 + jr) * HW + wq);

        if (tid >= 224 && tid < 480) {         // interior H: rows 14..45 (local data)
            const int id = tid - 224;          // 0..255
            const int j  = 14 + (id >> 3);
            const int s  = (id & 7) << 3;
            h_segment(&R_nxt[j * RP], H29, H9, j, s);
        }

        if (tid < 224) {                       // deposit halo registers
            float* rp = &R_nxt[(pj0 + jr) * RP + wq];
            rp[0] = hv.x; rp[1] = hv.y; rp[2] = hv.z; rp[3] = hv.w;
        }
        __syncthreads();

        if (tid < 112) {                       // partner-row H: 14 rows x 8 segments
            const int j = pj0 + (tid >> 3);
            const int s = (tid & 7) << 3;
            h_segment(&R_nxt[j * RP], H29, H9, j, s);
        }

        // batch-barrier wait (mostly satisfied — hidden behind shadow work)
        if (tid == 0) {
            while ((int)(ld_acq(&g_bar_gen[n]) - gtgt) < 0) { }
        }
        __syncthreads();
    }
}

extern "C" void kernel_launch(void* const* d_in, const int* in_sizes, int n_in,
                              void* d_out, int out_size)
{
    const float* inbound = (const float*)d_in[0];
    const float* Wf      = (const float*)d_in[1];
    const float* bf      = (const float*)d_in[2];
    const float* Ws      = (const float*)d_in[3];
    const float* bs      = (const float*)d_in[4];
    float* out = (float*)d_out;

    const int smem_bytes = (4 * ROWS_L * RP + 32 * HW + KCH) * sizeof(float) + 16;
    static bool attr_set = false;
    if (!attr_set) {
        cudaFuncSetAttribute(persist_kernel,
                             cudaFuncAttributeMaxDynamicSharedMemorySize, smem_bytes);
        attr_set = true;
    }
    persist_kernel<<<NCTA, NTHR, smem_bytes>>>(inbound, Wf, bf, Ws, bs, out);
}

// round 14
// speedup vs baseline: 2.0605x; 1.3514x over previous
#include <cuda_runtime.h>

#define KCH    32
#define HW     64
#define TSTEPS 100
#define PLANE  4096
#define NCTA   128
#define NCTA_B 64          // CTAs per batch (independent barrier groups)
#define NTHR   512
#define ROWS_L 60
#define RP     65

// State X_{t+1} lives directly in out[n, t, k, :, :].
// Per-batch barrier (atomicAdd arrive + gen release) + per-CTA partner flags.
// gen/flags monotonic across graph replays (relative compares only); cnt reset
// to 0 by each releaser. Release ordering: st.release / atomic RMW order all
// prior stores (no separate membar needed).
__device__ unsigned g_bar_cnt[2], g_bar_gen[2];
__device__ unsigned g_flags[NCTA];

__device__ __forceinline__ unsigned ld_acq(const unsigned* p) {
    unsigned v;
    asm volatile("ld.acquire.gpu.global.u32 %0, [%1];" : "=r"(v) : "l"(p) : "memory");
    return v;
}
__device__ __forceinline__ void st_rel(unsigned* p, unsigned v) {
    asm volatile("st.release.gpu.global.u32 [%0], %1;" :: "l"(p), "r"(v) : "memory");
}
__device__ __forceinline__ unsigned atom_add_rel(unsigned* p, unsigned v) {
    unsigned old;
    asm volatile("atom.add.release.gpu.global.u32 %0, [%1], %2;"
                 : "=r"(old) : "l"(p), "r"(v) : "memory");
    return old;
}

__global__ void __launch_bounds__(NTHR, 1)
persist_kernel(const float* __restrict__ inbound,
               const float* __restrict__ Wf,
               const float* __restrict__ bf,
               const float* __restrict__ Ws,
               const float* __restrict__ bs,
               float* __restrict__ out)
{
    extern __shared__ float sm[];
    float* Rb0 = sm;                           // [60][65] X halo rows (even t)
    float* Rb1 = Rb0 + ROWS_L * RP;            // [60][65] X halo rows (odd t)
    float* H29 = Rb1 + ROWS_L * RP;            // [60][65] inh * 29-wide horiz sums
    float* H9  = H29 + ROWS_L * RP;            // [60][65] emin * 9-wide horiz sums
    float* S   = H9  + ROWS_L * RP;            // [32][64] feat + 0.5*inb + bf
    float* WfS = S + 32 * HW;
    __shared__ unsigned sb[2];

    const int b   = blockIdx.x;                // 0..127
    const int tid = threadIdx.x;
    const int n   = b >> 6;
    const int k   = (b & 63) >> 1;
    const int h   = b & 1;
    const int r0  = h << 5;
    const int partner = b ^ 1;
    const size_t plane_off = (size_t)k * PLANE;

    if (tid < KCH) WfS[tid] = Wf[k * KCH + tid];
    if (tid == 0) { sb[0] = ld_acq(&g_bar_gen[n]); sb[1] = ld_acq(&g_flags[b]); }

    const float bf_k = bf[k];
    const float bs_k = bs[k];
    const float inh  = Ws[k * 841];                 // uniform inhibition value
    const float emin = Ws[k * 841 + 420] - inh;     // center excitation minus inh

    // zero R buffers + H29 + H9 (X_0 = 0; zero-edge-row H entries never rewritten)
    for (int i = tid; i < 4 * ROWS_L * RP; i += NTHR) sm[i] = 0.f;

    // ---- feat mapping: (row rr_f, 4 contiguous pixels) ----
    const int rr_f = tid >> 4;                 // 0..31
    const int w0_f = (tid & 15) << 2;
    const float4 inb4 = *(const float4*)(inbound + (size_t)(n * KCH + k) * PLANE
                                         + (r0 + rr_f) * HW + w0_f);
    const float base0 = 0.5f * inb4.x + bf_k;
    const float base1 = 0.5f * inb4.y + bf_k;
    const float base2 = 0.5f * inb4.z + bf_k;
    const float base3 = 0.5f * inb4.w + bf_k;
    *(float4*)&S[rr_f * HW + w0_f] = make_float4(base0, base1, base2, base3);

    // ---- partner-halo mapping: 14 rows x 16 float4 = 224 items ----
    // h=0: global rows 32..45 -> j=46..59 ; h=1: global rows 18..31 -> j=0..13
    const int pj0 = h ? 0 : 46;
    const int pg0 = h ? 18 : 32;
    const int jr  = tid >> 4;                  // valid for tid<224
    const int wq  = (tid & 15) << 2;

    // ---- H mapping ----
    const int j_h = tid >> 3;                  // 0..63 (active <60)
    const int s_h = (tid & 7) << 3;

    // ---- V mapping: 512 threads, (column, 4-row segment) ----
    const int w_v = tid & 63;
    const int rb  = (tid >> 6) << 2;

    __syncthreads();
    const unsigned gen0 = sb[0], fbase = sb[1];

    for (int t = 0; t < TSTEPS; t++) {
        float* R_cur = (t & 1) ? Rb1 : Rb0;
        float* R_nxt = (t & 1) ? Rb0 : Rb1;
        const float* frame_prev = out + ((size_t)(n * TSTEPS + t - 1) * KCH) * PLANE;
        float*       frame_cur  = out + ((size_t)(n * TSTEPS + t)     * KCH) * PLANE;

        // ======== feat (t>0): S = base + Wf @ X_t ========
        if (t > 0) {
            const float4* bp = (const float4*)(frame_prev + (r0 + rr_f) * HW + w0_f);
            float a0 = base0, a1 = base1, a2 = base2, a3 = base3;
            #pragma unroll
            for (int i = 0; i < KCH; i++) {
                const float wv = WfS[i];
                const float4 x = bp[i * (PLANE / 4)];
                a0 += wv * x.x; a1 += wv * x.y;
                a2 += wv * x.z; a3 += wv * x.w;
            }
            *(float4*)&S[rr_f * HW + w0_f] = make_float4(a0, a1, a2, a3);
            __syncthreads();
        }

        // ======== V: vertical box sums (H prescaled) + combine ========
        {
            // hoist xo reads ahead of the accumulation chains
            float xo[4];
            #pragma unroll
            for (int r = 0; r < 4; r++) xo[r] = R_cur[(rb + r + 14) * RP + w_v];

            float b29a = 0.f, b29b = 0.f, b9 = 0.f;
            #pragma unroll
            for (int d = 0; d < 14; d++) {
                b29a += H29[(rb + d) * RP + w_v];
                b29b += H29[(rb + 14 + d) * RP + w_v];
            }
            float b29 = b29a + b29b + H29[(rb + 28) * RP + w_v];
            #pragma unroll
            for (int d = 0; d < 9; d++) b9 += H9[(rb + 10 + d) * RP + w_v];

            #pragma unroll
            for (int r = 0; r < 4; r++) {
                const int rr = rb + r;
                const int j  = rr + 14;
                if (r > 0) {
                    b29 += H29[(rr + 28) * RP + w_v] - H29[(rr - 1) * RP + w_v];
                    b9  += H9 [(j + 4)  * RP + w_v] - H9 [(j - 5)  * RP + w_v];
                }
                const float S_total = S[rr * HW + w_v] + b29 + b9 + bs_k;
                const float xn = 0.8f * xo[r] + 0.2f * fmaxf(S_total, 0.f);
                R_nxt[j * RP + w_v] = xn;                  // interior rows for t+1
                frame_cur[plane_off + (size_t)(r0 + rr) * HW + w_v] = xn;
            }
        }

        if (t == TSTEPS - 1) break;

        __syncthreads();                       // frame/R_nxt stores + smem reads done
        const unsigned ftgt = fbase + (unsigned)t + 1u;
        const unsigned gtgt = gen0  + (unsigned)t + 1u;
        if (tid == 0) {
            st_rel(&g_flags[b], ftgt);         // release: orders prior frame stores
            if (atom_add_rel(&g_bar_cnt[n], 1u) == NCTA_B - 1) {
                g_bar_cnt[n] = 0;
                st_rel(&g_bar_gen[n], gtgt);
            }
            // wait only for partner before touching its halo rows
            while ((int)(ld_acq(&g_flags[partner]) - ftgt) < 0) { }
        }
        __syncthreads();

        // ======== partner halo rows of X_{t+1} -> R_nxt (barrier shadow) ========
        if (tid < 224) {
            const float4 v = *(const float4*)(frame_cur + plane_off
                                              + (pg0 + jr) * HW + wq);
            float* rp = &R_nxt[(pj0 + jr) * RP + wq];
            rp[0] = v.x; rp[1] = v.y; rp[2] = v.z; rp[3] = v.w;
        }
        __syncthreads();

        // ======== H for step t+1 (prescaled by inh / emin) ========
        if (j_h < ROWS_L) {
            float v[36];
            const float* row = &R_nxt[j_h * RP];
            #pragma unroll
            for (int d = 0; d < 36; d++) {
                const int w = s_h - 14 + d;
                v[d] = (w >= 0 && w < HW) ? row[w] : 0.f;
            }
            float sa = 0.f, sc = 0.f;
            #pragma unroll
            for (int d = 0; d < 14; d++) { sa += v[d]; sc += v[d + 14]; }
            float s29 = sa + sc + v[28];
            H29[j_h * RP + s_h] = inh * s29;
            #pragma unroll
            for (int p = 1; p < 8; p++) {
                s29 += v[p + 28] - v[p - 1];
                H29[j_h * RP + s_h + p] = inh * s29;
            }
            float s9 = 0.f;
            #pragma unroll
            for (int d = 10; d < 19; d++) s9 += v[d];
            H9[j_h * RP + s_h] = emin * s9;
            #pragma unroll
            for (int p = 1; p < 8; p++) {
                s9 += v[p + 18] - v[p + 9];
                H9[j_h * RP + s_h + p] = emin * s9;
            }
        }

        // batch-barrier wait (mostly satisfied — hidden behind halo + H work)
        if (tid == 0) {
            while ((int)(ld_acq(&g_bar_gen[n]) - gtgt) < 0) { }
        }
        __syncthreads();
    }
}

extern "C" void kernel_launch(void* const* d_in, const int* in_sizes, int n_in,
                              void* d_out, int out_size)
{
    const float* inbound = (const float*)d_in[0];
    const float* Wf      = (const float*)d_in[1];
    const float* bf      = (const float*)d_in[2];
    const float* Ws      = (const float*)d_in[3];
    const float* bs      = (const float*)d_in[4];
    float* out = (float*)d_out;

    const int smem_bytes = (4 * ROWS_L * RP + 32 * HW + KCH) * sizeof(float) + 16;
    static bool attr_set = false;
    if (!attr_set) {
        cudaFuncSetAttribute(persist_kernel,
                             cudaFuncAttributeMaxDynamicSharedMemorySize, smem_bytes);
        attr_set = true;
    }
    persist_kernel<<<NCTA, NTHR, smem_bytes>>>(inbound, Wf, bf, Ws, bs, out);
}

// round 16
// speedup vs baseline: 2.0728x; 1.0060x over previous
#include <cuda_runtime.h>

#define KCH    32
#define HW     64
#define TSTEPS 100
#define PLANE  4096
#define NCTA   128
#define NTHR   512
#define ROWS_L 60
#define RP     65

// State X_{t+1} lives directly in out[n, t, k, :, :].
// Sync: per-(n,half) group barrier (32 arrivals; atomicAdd arrive + gen
// release) gates feat; per-CTA partner flags gate halo/H. gen/flags monotonic
// across graph replays (relative compares only); cnt reset by each releaser.
__device__ unsigned g_cnt[4], g_gen[4];
__device__ unsigned g_flags[NCTA];

__device__ __forceinline__ unsigned ld_acq(const unsigned* p) {
    unsigned v;
    asm volatile("ld.acquire.gpu.global.u32 %0, [%1];" : "=r"(v) : "l"(p) : "memory");
    return v;
}
__device__ __forceinline__ void st_rel(unsigned* p, unsigned v) {
    asm volatile("st.release.gpu.global.u32 [%0], %1;" :: "l"(p), "r"(v) : "memory");
}

__global__ void __launch_bounds__(NTHR, 1)
persist_kernel(const float* __restrict__ inbound,
               const float* __restrict__ Wf,
               const float* __restrict__ bf,
               const float* __restrict__ Ws,
               const float* __restrict__ bs,
               float* __restrict__ out)
{
    extern __shared__ float sm[];
    float* Rb0 = sm;                           // [60][65] X halo rows (even t)
    float* Rb1 = Rb0 + ROWS_L * RP;            // [60][65] X halo rows (odd t)
    float* H29 = Rb1 + ROWS_L * RP;            // [60][65] 29-wide horizontal sums
    float* H9  = H29 + ROWS_L * RP;            // [60][65] 9-wide horizontal sums
    float* S   = H9  + ROWS_L * RP;            // [32][64] feat + 0.5*inb + bf
    float* WfS = S + 32 * HW;
    __shared__ unsigned sb[2];

    const int b   = blockIdx.x;                // 0..127
    const int tid = threadIdx.x;
    const int n   = b >> 6;
    const int k   = (b & 63) >> 1;
    const int h   = b & 1;
    const int r0  = h << 5;
    const int partner = b ^ 1;
    const int g   = n * 2 + h;                 // barrier group (32 CTAs)
    const size_t plane_off = (size_t)k * PLANE;

    if (tid < KCH) WfS[tid] = Wf[k * KCH + tid];
    if (tid == 0) { sb[0] = ld_acq(&g_gen[g]); sb[1] = ld_acq(&g_flags[b]); }

    const float bf_k = bf[k];
    const float bs_k = bs[k];
    const float inh  = Ws[k * 841];                 // uniform inhibition value
    const float emin = Ws[k * 841 + 420] - inh;     // center excitation minus inh

    // zero R buffers + H29 + H9 (X_0 = 0; zero-edge-row H entries never rewritten)
    for (int i = tid; i < 4 * ROWS_L * RP; i += NTHR) sm[i] = 0.f;

    // ---- feat mapping: (row rr_f, 4 contiguous pixels) ----
    const int rr_f = tid >> 4;                 // 0..31
    const int w0_f = (tid & 15) << 2;
    const float4 inb4 = *(const float4*)(inbound + (size_t)(n * KCH + k) * PLANE
                                         + (r0 + rr_f) * HW + w0_f);
    const float base0 = 0.5f * inb4.x + bf_k;
    const float base1 = 0.5f * inb4.y + bf_k;
    const float base2 = 0.5f * inb4.z + bf_k;
    const float base3 = 0.5f * inb4.w + bf_k;
    *(float4*)&S[rr_f * HW + w0_f] = make_float4(base0, base1, base2, base3);

    // ---- partner-halo mapping: 14 rows x 16 float4 = 224 items ----
    // h=0: global rows 32..45 -> j=46..59 ; h=1: global rows 18..31 -> j=0..13
    const int pj0 = h ? 0 : 46;
    const int pg0 = h ? 18 : 32;
    const int jr  = tid >> 4;                  // valid for tid<224
    const int wq  = (tid & 15) << 2;

    // ---- H mapping ----
    const int j_h = tid >> 3;                  // 0..63 (active <60)
    const int s_h = (tid & 7) << 3;

    // ---- V mapping: 512 threads, (column, 4-row segment) ----
    const int w_v = tid & 63;
    const int rb  = (tid >> 6) << 2;

    __syncthreads();
    const unsigned gen0 = sb[0], fbase = sb[1];

    for (int t = 0; t < TSTEPS; t++) {
        float* R_cur = (t & 1) ? Rb1 : Rb0;
        float* R_nxt = (t & 1) ? Rb0 : Rb1;
        const float* frame_prev = out + ((size_t)(n * TSTEPS + t - 1) * KCH) * PLANE;
        float*       frame_cur  = out + ((size_t)(n * TSTEPS + t)     * KCH) * PLANE;

        // ======== feat (t>0): S = base + Wf @ X_t ========
        if (t > 0) {
            const float4* bp = (const float4*)(frame_prev + (r0 + rr_f) * HW + w0_f);
            float a0 = base0, a1 = base1, a2 = base2, a3 = base3;
            #pragma unroll
            for (int i = 0; i < KCH; i++) {
                const float wv = WfS[i];
                const float4 x = bp[i * (PLANE / 4)];
                a0 += wv * x.x; a1 += wv * x.y;
                a2 += wv * x.z; a3 += wv * x.w;
            }
            *(float4*)&S[rr_f * HW + w0_f] = make_float4(a0, a1, a2, a3);
            __syncthreads();
        }

        // ======== V: vertical box sums (H from previous tail) + combine ========
        {
            float b29a = 0.f, b29b = 0.f, b9 = 0.f;
            #pragma unroll
            for (int d = 0; d < 14; d++) {
                b29a += H29[(rb + d) * RP + w_v];
                b29b += H29[(rb + 14 + d) * RP + w_v];
            }
            float b29 = b29a + b29b + H29[(rb + 28) * RP + w_v];
            #pragma unroll
            for (int d = 0; d < 9; d++) b9 += H9[(rb + 10 + d) * RP + w_v];

            #pragma unroll
            for (int r = 0; r < 4; r++) {
                const int rr = rb + r;
                const int j  = rr + 14;
                if (r > 0) {
                    b29 += H29[(rr + 28) * RP + w_v] - H29[(rr - 1) * RP + w_v];
                    b9  += H9 [(j + 4)  * RP + w_v] - H9 [(j - 5)  * RP + w_v];
                }
                const float sp = inh * b29 + emin * b9 + bs_k;
                const float xo = R_cur[j * RP + w_v];
                const float xn = 0.8f * xo + 0.2f * fmaxf(S[rr * HW + w_v] + sp, 0.f);
                R_nxt[j * RP + w_v] = xn;                  // interior rows for t+1
                frame_cur[plane_off + (size_t)(r0 + rr) * HW + w_v] = xn;
            }
        }

        if (t == TSTEPS - 1) break;

        __syncthreads();                       // frame/R_nxt stores + smem reads done
        const unsigned ftgt = fbase + (unsigned)t + 1u;
        const unsigned gtgt = gen0  + (unsigned)t + 1u;
        if (tid == 0) {
            __threadfence();                   // publish this CTA's frame stores
            st_rel(&g_flags[b], ftgt);
            if (atomicAdd(&g_cnt[g], 1u) == 31u) {
                g_cnt[g] = 0;
                st_rel(&g_gen[g], gtgt);
            }
            // wait only for partner before touching its halo rows
            while ((int)(ld_acq(&g_flags[partner]) - ftgt) < 0) { }
        }
        __syncthreads();

        // ======== partner halo rows of X_{t+1} -> R_nxt (barrier shadow) ========
        if (tid < 224) {
            const float4 v = *(const float4*)(frame_cur + plane_off
                                              + (pg0 + jr) * HW + wq);
            float* rp = &R_nxt[(pj0 + jr) * RP + wq];
            rp[0] = v.x; rp[1] = v.y; rp[2] = v.z; rp[3] = v.w;
        }
        __syncthreads();

        // ======== H for step t+1 from R_nxt (barrier shadow) ========
        if (j_h < ROWS_L) {
            float v[36];
            const float* row = &R_nxt[j_h * RP];
            #pragma unroll
            for (int d = 0; d < 36; d++) {
                const int w = s_h - 14 + d;
                v[d] = (w >= 0 && w < HW) ? row[w] : 0.f;
            }
            float sa = 0.f, sc = 0.f;
            #pragma unroll
            for (int d = 0; d < 14; d++) { sa += v[d]; sc += v[d + 14]; }
            float s29 = sa + sc + v[28];
            H29[j_h * RP + s_h] = s29;
            #pragma unroll
            for (int p = 1; p < 8; p++) {
                s29 += v[p + 28] - v[p - 1];
                H29[j_h * RP + s_h + p] = s29;
            }
            float s9 = 0.f;
            #pragma unroll
            for (int d = 10; d < 19; d++) s9 += v[d];
            H9[j_h * RP + s_h] = s9;
            #pragma unroll
            for (int p = 1; p < 8; p++) {
                s9 += v[p + 18] - v[p + 9];
                H9[j_h * RP + s_h + p] = s9;
            }
        }

        // group-barrier wait (mostly satisfied — hidden behind halo + H work)
        if (tid == 0) {
            while ((int)(ld_acq(&g_gen[g]) - gtgt) < 0) { }
        }
        __syncthreads();
    }
}

extern "C" void kernel_launch(void* const* d_in, const int* in_sizes, int n_in,
                              void* d_out, int out_size)
{
    const float* inbound = (const float*)d_in[0];
    const float* Wf      = (const float*)d_in[1];
    const float* bf      = (const float*)d_in[2];
    const float* Ws      = (const float*)d_in[3];
    const float* bs      = (const float*)d_in[4];
    float* out = (float*)d_out;

    const int smem_bytes = (4 * ROWS_L * RP + 32 * HW + KCH) * sizeof(float) + 16;
    static bool attr_set = false;
    if (!attr_set) {
        cudaFuncSetAttribute(persist_kernel,
                             cudaFuncAttributeMaxDynamicSharedMemorySize, smem_bytes);
        attr_set = true;
    }
    persist_kernel<<<NCTA, NTHR, smem_bytes>>>(inbound, Wf, bf, Ws, bs, out);
}